// round 9
// baseline (speedup 1.0000x reference)
#include <cuda_runtime.h>
#include <cuda_fp16.h>
#include <cstdint>

// ---------------------------------------------------------------------------
// GQA causal flash attention (prefill), fp16 mma.sync m16n8k16 + ldmatrix.
// S=2048, 32 Q heads / 8 KV heads, D=128, fp32 in/out.
// 512 threads / CTA = 16 warps = 8 teams of 2. Team t owns q-rows
// [t*16, t*16+16); both warps compute full S (redundant GEMM1) and split
// GEMM2 output along head_dim (64 cols each). Q pre-scaled fp16 in smem,
// fragments reloaded via ldmatrix each tile; K/V fp16 gmem scratch staged
// via cp.async double buffer.
// ---------------------------------------------------------------------------

#define NUM_HEADS 32
#define HEAD_DIM  128
#define QSTRIDE   4096
#define KSTRIDE   1024
#define BR 128
#define BC 64
#define NTHREADS 512

// smem: [Q 32KB][K0 16KB][K1 16KB][V0 16KB][V1 16KB]
#define SM_K0 32768u
#define SM_V0 65536u
#define SMEM_BYTES (32768 + 4 * 16384)

__device__ __half d_Kh[2048 * 1024];
__device__ __half d_Vh[2048 * 1024];

static __device__ __forceinline__ uint32_t smem_u32(const void* p) {
    uint32_t a;
    asm("{ .reg .u64 t; cvta.to.shared.u64 t, %1; cvt.u32.u64 %0, t; }" : "=r"(a) : "l"(p));
    return a;
}
static __device__ __forceinline__ float ex2f(float x) {
    float y; asm("ex2.approx.ftz.f32 %0, %1;" : "=f"(y) : "f"(x)); return y;
}
static __device__ __forceinline__ unsigned packh2(float lo, float hi) {
    __half2 h = __floats2half2_rn(lo, hi);
    return *reinterpret_cast<unsigned*>(&h);
}
static __device__ __forceinline__ void mma_f16(float* c, const unsigned* a,
                                               unsigned b0, unsigned b1) {
    asm("mma.sync.aligned.m16n8k16.row.col.f32.f16.f16.f32 "
        "{%0,%1,%2,%3}, {%4,%5,%6,%7}, {%8,%9}, {%0,%1,%2,%3};"
        : "+f"(c[0]), "+f"(c[1]), "+f"(c[2]), "+f"(c[3])
        : "r"(a[0]), "r"(a[1]), "r"(a[2]), "r"(a[3]), "r"(b0), "r"(b1));
}
static __device__ __forceinline__ void ldsm4(unsigned& r0, unsigned& r1,
                                             unsigned& r2, unsigned& r3, uint32_t addr) {
    asm volatile("ldmatrix.sync.aligned.m8n8.x4.shared.b16 {%0,%1,%2,%3}, [%4];"
                 : "=r"(r0), "=r"(r1), "=r"(r2), "=r"(r3) : "r"(addr));
}
static __device__ __forceinline__ void ldsm4t(unsigned& r0, unsigned& r1,
                                              unsigned& r2, unsigned& r3, uint32_t addr) {
    asm volatile("ldmatrix.sync.aligned.m8n8.x4.trans.shared.b16 {%0,%1,%2,%3}, [%4];"
                 : "=r"(r0), "=r"(r1), "=r"(r2), "=r"(r3) : "r"(addr));
}
static __device__ __forceinline__ void cpa16(uint32_t dst, const void* src) {
    asm volatile("cp.async.cg.shared.global [%0], [%1], 16;"
                 :: "r"(dst), "l"(__cvta_generic_to_global(src)) : "memory");
}
#define CP_COMMIT() asm volatile("cp.async.commit_group;" ::: "memory")
#define CP_WAIT1()  asm volatile("cp.async.wait_group 1;" ::: "memory")
#define CP_WAIT0()  asm volatile("cp.async.wait_group 0;" ::: "memory")

// ---- pre-pass: fp32 -> fp16 for K and V ----
__global__ void __launch_bounds__(256, 4)
cvt_kv(const float* __restrict__ K, const float* __restrict__ V)
{
    size_t i = ((size_t)blockIdx.x * 256 + threadIdx.x) * 8;
    float4 a = *reinterpret_cast<const float4*>(K + i);
    float4 b = *reinterpret_cast<const float4*>(K + i + 4);
    __half2 h0 = __floats2half2_rn(a.x, a.y), h1 = __floats2half2_rn(a.z, a.w);
    __half2 h2 = __floats2half2_rn(b.x, b.y), h3 = __floats2half2_rn(b.z, b.w);
    uint4 o;
    o.x = *reinterpret_cast<unsigned*>(&h0); o.y = *reinterpret_cast<unsigned*>(&h1);
    o.z = *reinterpret_cast<unsigned*>(&h2); o.w = *reinterpret_cast<unsigned*>(&h3);
    *reinterpret_cast<uint4*>(d_Kh + i) = o;
    a = *reinterpret_cast<const float4*>(V + i);
    b = *reinterpret_cast<const float4*>(V + i + 4);
    h0 = __floats2half2_rn(a.x, a.y); h1 = __floats2half2_rn(a.z, a.w);
    h2 = __floats2half2_rn(b.x, b.y); h3 = __floats2half2_rn(b.z, b.w);
    o.x = *reinterpret_cast<unsigned*>(&h0); o.y = *reinterpret_cast<unsigned*>(&h1);
    o.z = *reinterpret_cast<unsigned*>(&h2); o.w = *reinterpret_cast<unsigned*>(&h3);
    *reinterpret_cast<uint4*>(d_Vh + i) = o;
}

__global__ void __launch_bounds__(NTHREADS, 1)
fa_f16_v6(const float* __restrict__ Q, float* __restrict__ O)
{
    extern __shared__ char sm[];
    const uint32_t sb = smem_u32(sm);

    const int iq   = (int)gridDim.x - 1 - (int)blockIdx.x;   // longest first
    const int h    = blockIdx.y;
    const int g    = h >> 2;
    const int tid  = threadIdx.x;
    const int w    = tid >> 5;
    const int team = w >> 1;            // 0..7 -> 16-row strip
    const int half = w & 1;             // head-dim half for GEMM2/output
    const int lane = tid & 31;
    const int gid  = lane >> 2;
    const int t4   = lane & 3;
    const int strip  = team * 16;
    const int qrow0  = iq * BR;
    const int row0   = qrow0 + strip + gid;
    const int row1   = row0 + 8;
    const int maxrow = qrow0 + strip + 15;

    // ldmatrix per-lane address pieces
    const int rin = lane & 7;
    const int khi = (lane >> 3) & 1;
    const int qhi = (lane >> 4) & 1;
    const int sel = lane >> 3;          // 0..3
    const uint32_t g1base = (uint32_t)((qhi * 8 + rin) * 256);   // K frag rows
    const uint32_t g2base = (uint32_t)((khi * 8 + rin) * 256);   // V frag rows
    const uint32_t qlbase = (uint32_t)((strip + rin + (sel & 1) * 8) * 256);
    const int qcsel = sel >> 1;

    // ---- stage tile 0 (K/V fp16 via cp.async) ----
    {
        const __half* kg = d_Kh + (size_t)g * 128;
        const __half* vg = d_Vh + (size_t)g * 128;
        #pragma unroll
        for (int t = 0; t < 2; ++t) {
            int idx = tid + t * NTHREADS;
            int r = idx >> 4, c16 = idx & 15;
            uint32_t dst = (uint32_t)(r * 256 + ((c16 ^ (r & 7)) << 4));
            cpa16(sb + SM_K0 + dst, kg + (size_t)r * KSTRIDE + c16 * 8);
            cpa16(sb + SM_V0 + dst, vg + (size_t)r * KSTRIDE + c16 * 8);
        }
        CP_COMMIT();
    }

    // ---- stage Q to smem (fp16, pre-scaled by softmax_scale * log2(e)) ----
    {
        const float sc = (float)(0.08838834764831845 * 1.4426950408889634);
        const float* qg = Q + (size_t)qrow0 * QSTRIDE + h * HEAD_DIM;
        #pragma unroll
        for (int t = 0; t < 4; ++t) {
            int idx = tid + t * NTHREADS;
            int r = idx >> 4, c16 = idx & 15;
            const float* src = qg + (size_t)r * QSTRIDE + c16 * 8;
            float4 a = *reinterpret_cast<const float4*>(src);
            float4 b = *reinterpret_cast<const float4*>(src + 4);
            __half2 h0 = __floats2half2_rn(a.x * sc, a.y * sc);
            __half2 h1 = __floats2half2_rn(a.z * sc, a.w * sc);
            __half2 h2 = __floats2half2_rn(b.x * sc, b.y * sc);
            __half2 h3 = __floats2half2_rn(b.z * sc, b.w * sc);
            uint4 o4;
            o4.x = *reinterpret_cast<unsigned*>(&h0);
            o4.y = *reinterpret_cast<unsigned*>(&h1);
            o4.z = *reinterpret_cast<unsigned*>(&h2);
            o4.w = *reinterpret_cast<unsigned*>(&h3);
            *reinterpret_cast<uint4*>(sm + r * 256 + ((c16 ^ (r & 7)) << 4)) = o4;
        }
    }

    float m0 = -1e30f, m1 = -1e30f, l0 = 0.f, l1 = 0.f;
    float o[8][4];
    #pragma unroll
    for (int nt = 0; nt < 8; ++nt)
        o[nt][0] = o[nt][1] = o[nt][2] = o[nt][3] = 0.f;

    const int jend = 2 * iq + 1;

    for (int j = 0; j <= jend; ++j) {
        if (j < jend) {
            int b = (j + 1) & 1;
            const __half* kg = d_Kh + (size_t)((j + 1) * BC) * KSTRIDE + g * 128;
            const __half* vg = d_Vh + (size_t)((j + 1) * BC) * KSTRIDE + g * 128;
            uint32_t kd = sb + SM_K0 + (uint32_t)b * 16384u;
            uint32_t vd = sb + SM_V0 + (uint32_t)b * 16384u;
            #pragma unroll
            for (int t = 0; t < 2; ++t) {
                int idx = tid + t * NTHREADS;
                int r = idx >> 4, c16 = idx & 15;
                uint32_t dst = (uint32_t)(r * 256 + ((c16 ^ (r & 7)) << 4));
                cpa16(kd + dst, kg + (size_t)r * KSTRIDE + c16 * 8);
                cpa16(vd + dst, vg + (size_t)r * KSTRIDE + c16 * 8);
            }
            CP_COMMIT();
            CP_WAIT1();
        } else {
            CP_WAIT0();
        }
        __syncthreads();

        const uint32_t kb = sb + SM_K0 + (uint32_t)(j & 1) * 16384u;
        const uint32_t vb = sb + SM_V0 + (uint32_t)(j & 1) * 16384u;

        const int d = maxrow - BC * j;
        if (d >= 0) {
            // ---- GEMM1: S = Q @ K^T (A via ldmatrix from Q smem, B via ldmatrix) ----
            float s[8][4];
            #pragma unroll
            for (int nt = 0; nt < 8; ++nt)
                s[nt][0] = s[nt][1] = s[nt][2] = s[nt][3] = 0.f;

            #pragma unroll
            for (int kc = 0; kc < 8; ++kc) {
                unsigned a[4];
                ldsm4(a[0], a[1], a[2], a[3],
                      sb + qlbase + (uint32_t)((((kc * 2 + qcsel) ^ rin) & 15) << 4));
                const int kch = kc * 2 + khi;
                #pragma unroll
                for (int ntp = 0; ntp < 4; ++ntp) {
                    if (16 * ntp <= d) {
                        unsigned b0, b1, b2, b3;
                        ldsm4(b0, b1, b2, b3,
                              kb + g1base + (uint32_t)(ntp * 4096) +
                              (uint32_t)(((kch ^ rin) & 15) << 4));
                        mma_f16(s[2 * ntp],     a, b0, b1);
                        mma_f16(s[2 * ntp + 1], a, b2, b3);
                    }
                }
            }

            // ---- mask + online softmax (log2 domain, warp-local) ----
            const bool diag = (j >= 2 * iq);
            float mx0 = -1e30f, mx1 = -1e30f;
            #pragma unroll
            for (int nt = 0; nt < 8; ++nt) {
                if (diag) {
                    int col = j * BC + nt * 8 + 2 * t4;
                    if (col     > row0) s[nt][0] = -1e30f;
                    if (col + 1 > row0) s[nt][1] = -1e30f;
                    if (col     > row1) s[nt][2] = -1e30f;
                    if (col + 1 > row1) s[nt][3] = -1e30f;
                }
                mx0 = fmaxf(mx0, fmaxf(s[nt][0], s[nt][1]));
                mx1 = fmaxf(mx1, fmaxf(s[nt][2], s[nt][3]));
            }
            mx0 = fmaxf(mx0, __shfl_xor_sync(0xffffffffu, mx0, 1));
            mx0 = fmaxf(mx0, __shfl_xor_sync(0xffffffffu, mx0, 2));
            mx1 = fmaxf(mx1, __shfl_xor_sync(0xffffffffu, mx1, 1));
            mx1 = fmaxf(mx1, __shfl_xor_sync(0xffffffffu, mx1, 2));

            const float nm0 = fmaxf(m0, mx0);
            const float nm1 = fmaxf(m1, mx1);
            const float cf0 = ex2f(m0 - nm0);
            const float cf1 = ex2f(m1 - nm1);
            m0 = nm0; m1 = nm1;

            float rs0 = 0.f, rs1 = 0.f;
            #pragma unroll
            for (int nt = 0; nt < 8; ++nt) {
                float p0 = ex2f(s[nt][0] - m0);
                float p1 = ex2f(s[nt][1] - m0);
                float p2 = ex2f(s[nt][2] - m1);
                float p3 = ex2f(s[nt][3] - m1);
                rs0 += p0 + p1; rs1 += p2 + p3;
                s[nt][0] = p0; s[nt][1] = p1; s[nt][2] = p2; s[nt][3] = p3;
            }
            rs0 += __shfl_xor_sync(0xffffffffu, rs0, 1);
            rs0 += __shfl_xor_sync(0xffffffffu, rs0, 2);
            rs1 += __shfl_xor_sync(0xffffffffu, rs1, 1);
            rs1 += __shfl_xor_sync(0xffffffffu, rs1, 2);
            l0 = l0 * cf0 + rs0;
            l1 = l1 * cf1 + rs1;

            #pragma unroll
            for (int nt = 0; nt < 8; ++nt) {
                o[nt][0] *= cf0; o[nt][1] *= cf0;
                o[nt][2] *= cf1; o[nt][3] *= cf1;
            }

            // ---- GEMM2: O(half) += P @ V[:, half*64 .. +64) ----
            #pragma unroll
            for (int kc2 = 0; kc2 < 4; ++kc2) {
                if (16 * kc2 <= d) {
                    unsigned a[4];
                    a[0] = packh2(s[2 * kc2][0],     s[2 * kc2][1]);
                    a[1] = packh2(s[2 * kc2][2],     s[2 * kc2][3]);
                    a[2] = packh2(s[2 * kc2 + 1][0], s[2 * kc2 + 1][1]);
                    a[3] = packh2(s[2 * kc2 + 1][2], s[2 * kc2 + 1][3]);
                    #pragma unroll
                    for (int ntp2 = 0; ntp2 < 4; ++ntp2) {
                        unsigned b0, b1, b2, b3;
                        ldsm4t(b0, b1, b2, b3,
                               vb + g2base + (uint32_t)(kc2 * 4096) +
                               (uint32_t)((((half * 8 + 2 * ntp2 + qhi) ^ rin) & 15) << 4));
                        mma_f16(o[2 * ntp2],     a, b0, b1);
                        mma_f16(o[2 * ntp2 + 1], a, b2, b3);
                    }
                }
            }
        }
        __syncthreads();
    }

    // ---- epilogue: normalize and store this warp's 64-col half ----
    const float inv0 = 1.f / l0;
    const float inv1 = 1.f / l1;
    float* ob0 = O + (size_t)row0 * QSTRIDE + h * HEAD_DIM + half * 64 + 2 * t4;
    float* ob1 = ob0 + (size_t)8 * QSTRIDE;
    #pragma unroll
    for (int nt = 0; nt < 8; ++nt) {
        float2 x0 = make_float2(o[nt][0] * inv0, o[nt][1] * inv0);
        float2 x1 = make_float2(o[nt][2] * inv1, o[nt][3] * inv1);
        *reinterpret_cast<float2*>(ob0 + nt * 8) = x0;
        *reinterpret_cast<float2*>(ob1 + nt * 8) = x1;
    }
}

extern "C" void kernel_launch(void* const* d_in, const int* in_sizes, int n_in,
                              void* d_out, int out_size)
{
    const float* Q = (const float*)d_in[0];
    const float* K = (const float*)d_in[1];
    const float* V = (const float*)d_in[2];
    float* O = (float*)d_out;

    cvt_kv<<<1024, 256>>>(K, V);

    cudaFuncSetAttribute(fa_f16_v6,
                         cudaFuncAttributeMaxDynamicSharedMemorySize, SMEM_BYTES);
    dim3 grid(2048 / BR, NUM_HEADS);
    fa_f16_v6<<<grid, NTHREADS, SMEM_BYTES>>>(Q, O);
}

// round 13
// speedup vs baseline: 1.2846x; 1.2846x over previous
#include <cuda_runtime.h>
#include <cuda_fp16.h>
#include <cstdint>

// ---------------------------------------------------------------------------
// GQA causal flash attention (prefill), fp16 mma.sync m16n8k16 + ldmatrix,
// software-pipelined: GEMM1 of tile j+1 overlaps softmax/GEMM2 of tile j.
// S=2048, 32 Q heads / 8 KV heads, D=128, fp32 in/out.
// Br=128 x Bc=64, 8 warps (256 thr), warp m-strip = 16 rows.
// Q pre-scaled fp16 in smem (ldmatrix A-frags); K/V fp16 gmem scratch,
// K staged 2 tiles ahead / V 1 tile ahead in separate cp.async groups.
// ---------------------------------------------------------------------------

#define NUM_HEADS 32
#define HEAD_DIM  128
#define QSTRIDE   4096
#define KSTRIDE   1024
#define BR 128
#define BC 64
#define NTHREADS 256

// smem: [Q 32KB][K0 16KB][K1 16KB][V0 16KB][V1 16KB]
#define SM_K0 32768u
#define SM_V0 65536u
#define SMEM_BYTES (32768 + 4 * 16384)

__device__ __half d_Kh[2048 * 1024];
__device__ __half d_Vh[2048 * 1024];

static __device__ __forceinline__ uint32_t smem_u32(const void* p) {
    uint32_t a;
    asm("{ .reg .u64 t; cvta.to.shared.u64 t, %1; cvt.u32.u64 %0, t; }" : "=r"(a) : "l"(p));
    return a;
}
static __device__ __forceinline__ float ex2f(float x) {
    float y; asm("ex2.approx.ftz.f32 %0, %1;" : "=f"(y) : "f"(x)); return y;
}
static __device__ __forceinline__ unsigned packh2(float lo, float hi) {
    __half2 h = __floats2half2_rn(lo, hi);
    return *reinterpret_cast<unsigned*>(&h);
}
static __device__ __forceinline__ void mma_f16(float* c, const unsigned* a,
                                               unsigned b0, unsigned b1) {
    asm("mma.sync.aligned.m16n8k16.row.col.f32.f16.f16.f32 "
        "{%0,%1,%2,%3}, {%4,%5,%6,%7}, {%8,%9}, {%0,%1,%2,%3};"
        : "+f"(c[0]), "+f"(c[1]), "+f"(c[2]), "+f"(c[3])
        : "r"(a[0]), "r"(a[1]), "r"(a[2]), "r"(a[3]), "r"(b0), "r"(b1));
}
static __device__ __forceinline__ void ldsm4(unsigned& r0, unsigned& r1,
                                             unsigned& r2, unsigned& r3, uint32_t addr) {
    asm volatile("ldmatrix.sync.aligned.m8n8.x4.shared.b16 {%0,%1,%2,%3}, [%4];"
                 : "=r"(r0), "=r"(r1), "=r"(r2), "=r"(r3) : "r"(addr));
}
static __device__ __forceinline__ void ldsm4t(unsigned& r0, unsigned& r1,
                                              unsigned& r2, unsigned& r3, uint32_t addr) {
    asm volatile("ldmatrix.sync.aligned.m8n8.x4.trans.shared.b16 {%0,%1,%2,%3}, [%4];"
                 : "=r"(r0), "=r"(r1), "=r"(r2), "=r"(r3) : "r"(addr));
}
static __device__ __forceinline__ void cpa16(uint32_t dst, const void* src) {
    asm volatile("cp.async.cg.shared.global [%0], [%1], 16;"
                 :: "r"(dst), "l"(__cvta_generic_to_global(src)) : "memory");
}
#define CP_COMMIT() asm volatile("cp.async.commit_group;" ::: "memory")
#define CP_WAIT2()  asm volatile("cp.async.wait_group 2;" ::: "memory")

// ---- pre-pass: fp32 -> fp16 for K and V ----
__global__ void __launch_bounds__(256, 4)
cvt_kv(const float* __restrict__ K, const float* __restrict__ V)
{
    size_t i = ((size_t)blockIdx.x * 256 + threadIdx.x) * 8;
    float4 a = *reinterpret_cast<const float4*>(K + i);
    float4 b = *reinterpret_cast<const float4*>(K + i + 4);
    __half2 h0 = __floats2half2_rn(a.x, a.y), h1 = __floats2half2_rn(a.z, a.w);
    __half2 h2 = __floats2half2_rn(b.x, b.y), h3 = __floats2half2_rn(b.z, b.w);
    uint4 o;
    o.x = *reinterpret_cast<unsigned*>(&h0); o.y = *reinterpret_cast<unsigned*>(&h1);
    o.z = *reinterpret_cast<unsigned*>(&h2); o.w = *reinterpret_cast<unsigned*>(&h3);
    *reinterpret_cast<uint4*>(d_Kh + i) = o;
    a = *reinterpret_cast<const float4*>(V + i);
    b = *reinterpret_cast<const float4*>(V + i + 4);
    h0 = __floats2half2_rn(a.x, a.y); h1 = __floats2half2_rn(a.z, a.w);
    h2 = __floats2half2_rn(b.x, b.y); h3 = __floats2half2_rn(b.z, b.w);
    o.x = *reinterpret_cast<unsigned*>(&h0); o.y = *reinterpret_cast<unsigned*>(&h1);
    o.z = *reinterpret_cast<unsigned*>(&h2); o.w = *reinterpret_cast<unsigned*>(&h3);
    *reinterpret_cast<uint4*>(d_Vh + i) = o;
}

// stage a 64x128 fp16 tile (16KB) with XOR-16B swizzle, 4 chunks/thread
static __device__ __forceinline__ void stage_tile(uint32_t dst, const __half* src, int tid) {
    #pragma unroll
    for (int t = 0; t < 4; ++t) {
        int idx = tid + t * NTHREADS;
        int r = idx >> 4, c16 = idx & 15;
        cpa16(dst + (uint32_t)(r * 256 + ((c16 ^ (r & 7)) << 4)),
              src + (size_t)r * KSTRIDE + c16 * 8);
    }
}

// GEMM1 for one kv tile: s = Q(strip) @ K^T, A-frags from Q smem via ldmatrix
static __device__ __forceinline__ void gemm1_tile(
    float s[8][4], uint32_t sb, uint32_t kb, int d,
    int rin, int khi, uint32_t g1base, uint32_t qlbase, int qcsel)
{
    #pragma unroll
    for (int nt = 0; nt < 8; ++nt)
        s[nt][0] = s[nt][1] = s[nt][2] = s[nt][3] = 0.f;
    #pragma unroll
    for (int kc = 0; kc < 8; ++kc) {
        unsigned a[4];
        ldsm4(a[0], a[1], a[2], a[3],
              sb + qlbase + (uint32_t)((((kc * 2 + qcsel) ^ rin) & 15) << 4));
        const int kch = kc * 2 + khi;
        #pragma unroll
        for (int ntp = 0; ntp < 4; ++ntp) {
            if (16 * ntp <= d) {
                unsigned b0, b1, b2, b3;
                ldsm4(b0, b1, b2, b3,
                      kb + g1base + (uint32_t)(ntp * 4096) +
                      (uint32_t)(((kch ^ rin) & 15) << 4));
                mma_f16(s[2 * ntp],     a, b0, b1);
                mma_f16(s[2 * ntp + 1], a, b2, b3);
            }
        }
    }
}

__global__ void __launch_bounds__(NTHREADS, 1)
fa_f16_v7(const float* __restrict__ Q, float* __restrict__ O)
{
    extern __shared__ char sm[];
    const uint32_t sb = smem_u32(sm);

    const int iq   = (int)gridDim.x - 1 - (int)blockIdx.x;   // longest first
    const int h    = blockIdx.y;
    const int g    = h >> 2;
    const int tid  = threadIdx.x;
    const int w    = tid >> 5;
    const int lane = tid & 31;
    const int gid  = lane >> 2;
    const int t4   = lane & 3;
    const int strip  = w * 16;
    const int qrow0  = iq * BR;
    const int row0   = qrow0 + strip + gid;
    const int row1   = row0 + 8;
    const int maxrow = qrow0 + strip + 15;

    // ldmatrix per-lane address pieces
    const int rin = lane & 7;
    const int khi = (lane >> 3) & 1;
    const int qhi = (lane >> 4) & 1;
    const int sel = lane >> 3;
    const uint32_t g1base = (uint32_t)((qhi * 8 + rin) * 256);
    const uint32_t g2base = (uint32_t)((khi * 8 + rin) * 256);
    const uint32_t qlbase = (uint32_t)((strip + rin + (sel & 1) * 8) * 256);
    const int qcsel = sel >> 1;

    const int jend = 2 * iq + 1;   // >= 1 always

    // ---- prologue staging: K0 | V0 | K1 as three cp.async groups ----
    stage_tile(sb + SM_K0,          d_Kh + (size_t)g * 128, tid);               CP_COMMIT();
    stage_tile(sb + SM_V0,          d_Vh + (size_t)g * 128, tid);               CP_COMMIT();
    stage_tile(sb + SM_K0 + 16384u, d_Kh + (size_t)BC * KSTRIDE + g * 128, tid); CP_COMMIT();

    // ---- stage Q to smem (fp16, pre-scaled by softmax_scale * log2(e)) ----
    {
        const float sc = (float)(0.08838834764831845 * 1.4426950408889634);
        const float* qg = Q + (size_t)qrow0 * QSTRIDE + h * HEAD_DIM;
        #pragma unroll
        for (int t = 0; t < 8; ++t) {
            int idx = tid + t * NTHREADS;
            int r = idx >> 4, c16 = idx & 15;
            const float* src = qg + (size_t)r * QSTRIDE + c16 * 8;
            float4 a = *reinterpret_cast<const float4*>(src);
            float4 b = *reinterpret_cast<const float4*>(src + 4);
            __half2 h0 = __floats2half2_rn(a.x * sc, a.y * sc);
            __half2 h1 = __floats2half2_rn(a.z * sc, a.w * sc);
            __half2 h2 = __floats2half2_rn(b.x * sc, b.y * sc);
            __half2 h3 = __floats2half2_rn(b.z * sc, b.w * sc);
            uint4 o4;
            o4.x = *reinterpret_cast<unsigned*>(&h0);
            o4.y = *reinterpret_cast<unsigned*>(&h1);
            o4.z = *reinterpret_cast<unsigned*>(&h2);
            o4.w = *reinterpret_cast<unsigned*>(&h3);
            *reinterpret_cast<uint4*>(sm + r * 256 + ((c16 ^ (r & 7)) << 4)) = o4;
        }
    }

    CP_WAIT2();            // K0 landed (V0, K1 still in flight)
    __syncthreads();

    float m0 = -1e30f, m1 = -1e30f, l0 = 0.f, l1 = 0.f;
    float o[16][4];
    #pragma unroll
    for (int nt = 0; nt < 16; ++nt)
        o[nt][0] = o[nt][1] = o[nt][2] = o[nt][3] = 0.f;

    // ---- pre-loop GEMM1 for tile 0 ----
    float sA[8][4];
    gemm1_tile(sA, sb, sb + SM_K0, maxrow, rin, khi, g1base, qlbase, qcsel);

    for (int j = 0; j <= jend; ++j) {
        // stage K_{j+2} (group), V_{j+1} (group); empty commits keep FIFO uniform
        if (j + 2 <= jend)
            stage_tile(sb + SM_K0 + (uint32_t)(j & 1) * 16384u,
                       d_Kh + (size_t)(j + 2) * BC * KSTRIDE + g * 128, tid);
        CP_COMMIT();
        if (j + 1 <= jend)
            stage_tile(sb + SM_V0 + (uint32_t)((j + 1) & 1) * 16384u,
                       d_Vh + (size_t)(j + 1) * BC * KSTRIDE + g * 128, tid);
        CP_COMMIT();
        CP_WAIT2();        // retires {K_{j+1}, V_j}
        __syncthreads();

        const uint32_t vb = sb + SM_V0 + (uint32_t)(j & 1) * 16384u;

        // ---- GEMM1 for tile j+1 (overlaps softmax/G2 below) ----
        float sB[8][4];
        const int dn = maxrow - BC * (j + 1);
        if (j < jend && dn >= 0)
            gemm1_tile(sB, sb, sb + SM_K0 + (uint32_t)((j + 1) & 1) * 16384u,
                       dn, rin, khi, g1base, qlbase, qcsel);

        const int d = maxrow - BC * j;
        if (d >= 0) {
            // ---- mask + online softmax (log2 domain) on sA ----
            const bool diag = (j >= 2 * iq);
            float mx0 = -1e30f, mx1 = -1e30f;
            #pragma unroll
            for (int nt = 0; nt < 8; ++nt) {
                if (diag) {
                    int col = j * BC + nt * 8 + 2 * t4;
                    if (col     > row0) sA[nt][0] = -1e30f;
                    if (col + 1 > row0) sA[nt][1] = -1e30f;
                    if (col     > row1) sA[nt][2] = -1e30f;
                    if (col + 1 > row1) sA[nt][3] = -1e30f;
                }
                mx0 = fmaxf(mx0, fmaxf(sA[nt][0], sA[nt][1]));
                mx1 = fmaxf(mx1, fmaxf(sA[nt][2], sA[nt][3]));
            }
            mx0 = fmaxf(mx0, __shfl_xor_sync(0xffffffffu, mx0, 1));
            mx0 = fmaxf(mx0, __shfl_xor_sync(0xffffffffu, mx0, 2));
            mx1 = fmaxf(mx1, __shfl_xor_sync(0xffffffffu, mx1, 1));
            mx1 = fmaxf(mx1, __shfl_xor_sync(0xffffffffu, mx1, 2));

            const float nm0 = fmaxf(m0, mx0);
            const float nm1 = fmaxf(m1, mx1);
            const float cf0 = ex2f(m0 - nm0);
            const float cf1 = ex2f(m1 - nm1);
            m0 = nm0; m1 = nm1;

            float rs0 = 0.f, rs1 = 0.f;
            #pragma unroll
            for (int nt = 0; nt < 8; ++nt) {
                float p0 = ex2f(sA[nt][0] - m0);
                float p1 = ex2f(sA[nt][1] - m0);
                float p2 = ex2f(sA[nt][2] - m1);
                float p3 = ex2f(sA[nt][3] - m1);
                rs0 += p0 + p1; rs1 += p2 + p3;
                sA[nt][0] = p0; sA[nt][1] = p1; sA[nt][2] = p2; sA[nt][3] = p3;
            }
            // per-thread partial l (reduced across quad in epilogue)
            l0 = l0 * cf0 + rs0;
            l1 = l1 * cf1 + rs1;

            #pragma unroll
            for (int nt = 0; nt < 16; ++nt) {
                o[nt][0] *= cf0; o[nt][1] *= cf0;
                o[nt][2] *= cf1; o[nt][3] *= cf1;
            }

            // ---- GEMM2: O += P @ V (A = repacked sA, B via ldmatrix.trans) ----
            #pragma unroll
            for (int kc2 = 0; kc2 < 4; ++kc2) {
                if (16 * kc2 <= d) {
                    unsigned a[4];
                    a[0] = packh2(sA[2 * kc2][0],     sA[2 * kc2][1]);
                    a[1] = packh2(sA[2 * kc2][2],     sA[2 * kc2][3]);
                    a[2] = packh2(sA[2 * kc2 + 1][0], sA[2 * kc2 + 1][1]);
                    a[3] = packh2(sA[2 * kc2 + 1][2], sA[2 * kc2 + 1][3]);
                    #pragma unroll
                    for (int ntp2 = 0; ntp2 < 8; ++ntp2) {
                        unsigned b0, b1, b2, b3;
                        ldsm4t(b0, b1, b2, b3,
                               vb + g2base + (uint32_t)(kc2 * 4096) +
                               (uint32_t)((((2 * ntp2 + qhi) ^ rin) & 15) << 4));
                        mma_f16(o[2 * ntp2],     a, b0, b1);
                        mma_f16(o[2 * ntp2 + 1], a, b2, b3);
                    }
                }
            }
        }

        // rotate pipeline registers (compiler coalesces; sA dead here)
        #pragma unroll
        for (int nt = 0; nt < 8; ++nt) {
            sA[nt][0] = sB[nt][0]; sA[nt][1] = sB[nt][1];
            sA[nt][2] = sB[nt][2]; sA[nt][3] = sB[nt][3];
        }
        __syncthreads();
    }

    // ---- epilogue: reduce l across quad, normalize, store ----
    l0 += __shfl_xor_sync(0xffffffffu, l0, 1);
    l0 += __shfl_xor_sync(0xffffffffu, l0, 2);
    l1 += __shfl_xor_sync(0xffffffffu, l1, 1);
    l1 += __shfl_xor_sync(0xffffffffu, l1, 2);
    const float inv0 = 1.f / l0;
    const float inv1 = 1.f / l1;
    float* ob0 = O + (size_t)row0 * QSTRIDE + h * HEAD_DIM + 2 * t4;
    float* ob1 = ob0 + (size_t)8 * QSTRIDE;
    #pragma unroll
    for (int nt = 0; nt < 16; ++nt) {
        float2 x0 = make_float2(o[nt][0] * inv0, o[nt][1] * inv0);
        float2 x1 = make_float2(o[nt][2] * inv1, o[nt][3] * inv1);
        *reinterpret_cast<float2*>(ob0 + nt * 8) = x0;
        *reinterpret_cast<float2*>(ob1 + nt * 8) = x1;
    }
}

extern "C" void kernel_launch(void* const* d_in, const int* in_sizes, int n_in,
                              void* d_out, int out_size)
{
    const float* Q = (const float*)d_in[0];
    const float* K = (const float*)d_in[1];
    const float* V = (const float*)d_in[2];
    float* O = (float*)d_out;

    cvt_kv<<<1024, 256>>>(K, V);

    cudaFuncSetAttribute(fa_f16_v7,
                         cudaFuncAttributeMaxDynamicSharedMemorySize, SMEM_BYTES);
    dim3 grid(2048 / BR, NUM_HEADS);
    fa_f16_v7<<<grid, NTHREADS, SMEM_BYTES>>>(Q, O);
}